// round 14
// baseline (speedup 1.0000x reference)
#include <cuda_runtime.h>
#include <cuda_bf16.h>
#include <cstdint>
#include <math.h>

#define BATCH 16
#define TSEQ  1024
#define HD    1024
#define MTOT  (BATCH * TSEQ)   // 16384
#define G3H   (3 * HD)         // 3072
#define NCLS  128

__device__ __nv_bfloat16 g_h1[(size_t)MTOT * HD];    // layer-0 hidden seq
__device__ __nv_bfloat16 g_h2[(size_t)MTOT * HD];    // layer-1 hidden seq
__device__ __nv_bfloat16 g_a16[(size_t)MTOT * HD];   // gathered emb (bf16)
__device__ __nv_bfloat16 g_b16[(size_t)G3H * HD];    // head weights bf16
__device__ float g_lse[BATCH * NCLS];
__device__ unsigned g_cntv[128 * 32];                // per-CTA step counters (128B stride)

// ===========================================================================
// fp32 -> bf16 convert (optionally gathering rows via tok); rows are K=1024
// ===========================================================================
__global__ void __launch_bounds__(256) conv_bf16(
    const float* __restrict__ in, const int* __restrict__ tok,
    __nv_bfloat16* __restrict__ out, size_t total4)
{
    size_t idx = (size_t)blockIdx.x * blockDim.x + threadIdx.x;
    if (idx >= total4) return;
    size_t e = idx << 2;
    size_t m = e >> 10;
    int    k = (int)(e & 1023);
    size_t srow = tok ? (size_t)tok[m] : m;
    float4 v = *(const float4*)(in + srow * 1024 + k);
    __nv_bfloat162 p0 = __floats2bfloat162_rn(v.x, v.y);
    __nv_bfloat162 p1 = __floats2bfloat162_rn(v.z, v.w);
    *(__nv_bfloat162*)(out + e)     = p0;
    *(__nv_bfloat162*)(out + e + 2) = p1;
}

// ===========================================================================
// Shared helpers
// ===========================================================================
__device__ __forceinline__ uint32_t smem_u32(const void* p) {
    uint32_t a;
    asm("{ .reg .u64 t; cvta.to.shared.u64 t, %1; cvt.u32.u64 %0, t; }"
        : "=r"(a) : "l"(p));
    return a;
}

__device__ __forceinline__ void ldsm_x4(uint32_t* r, uint32_t addr) {
    asm volatile("ldmatrix.sync.aligned.m8n8.x4.shared.b16 {%0,%1,%2,%3}, [%4];"
                 : "=r"(r[0]), "=r"(r[1]), "=r"(r[2]), "=r"(r[3]) : "r"(addr));
}

__device__ __forceinline__ void mma16(float* d, const uint32_t* a, uint32_t b0, uint32_t b1) {
    asm volatile(
        "mma.sync.aligned.m16n8k16.row.col.f32.bf16.bf16.f32 "
        "{%0,%1,%2,%3}, {%4,%5,%6,%7}, {%8,%9}, {%0,%1,%2,%3};"
        : "+f"(d[0]), "+f"(d[1]), "+f"(d[2]), "+f"(d[3])
        : "r"(a[0]), "r"(a[1]), "r"(a[2]), "r"(a[3]), "r"(b0), "r"(b1));
}

__device__ __forceinline__ uint32_t pk_bf16x2(float lo, float hi) {
    __nv_bfloat162 p = __floats2bfloat162_rn(lo, hi);
    return *reinterpret_cast<uint32_t*>(&p);
}

__device__ __forceinline__ unsigned ld_acq(const unsigned* p) {
    unsigned v;
    asm volatile("ld.acquire.gpu.global.u32 %0, [%1];" : "=r"(v) : "l"(p) : "memory");
    return v;
}

__device__ __forceinline__ void st_rel(unsigned* p, unsigned v) {
    asm volatile("st.release.gpu.global.u32 [%0], %1;" :: "l"(p), "r"(v) : "memory");
}

__device__ __forceinline__ float fast_sigmoid(float x) {
    float e = __expf(fminf(fmaxf(-x, -80.f), 80.f));
    return __fdividef(1.f, 1.f + e);
}

__device__ __forceinline__ float fast_tanh(float x) {
    float u = __expf(fminf(fmaxf(-2.f * x, -80.f), 80.f));
    return __fdividef(1.f - u, 1.f + u);
}

// ===========================================================================
// bf16 mma.sync GEMM (validated R7) — head only
// ===========================================================================
#define RSTR_B 144
#define TILE_B (128 * RSTR_B)
#define GEMM_SMEM_BYTES (4 * TILE_B)

__global__ void __launch_bounds__(256) gemm_bf16(
    const __nv_bfloat16* __restrict__ A16,
    const __nv_bfloat16* __restrict__ B16,
    const float* __restrict__ bias,
    float* __restrict__ C, int N)
{
    extern __shared__ char smc[];
    const uint32_t sbase = smem_u32(smc);
    const int tid  = threadIdx.x;
    const int lane = tid & 31;
    const int warp = tid >> 5;
    const int bm = blockIdx.x * 128;
    const int bn = blockIdx.y * 128;
    const int wm = (warp & 1) * 64;
    const int wn = (warp >> 1) * 32;
    const int qr = lane >> 2;
    const int qc = lane & 3;

    const int r0 = tid >> 3;
    const int ch = tid & 7;
    const __nv_bfloat16* Ap = A16 + (size_t)(bm + r0) * 1024 + ch * 8;
    const __nv_bfloat16* Bp = B16 + (size_t)(bn + r0) * 1024 + ch * 8;
    const uint32_t s_off = (uint32_t)(r0 * RSTR_B + ch * 16);

    const uint32_t a_lm = (uint32_t)((wm + (lane & 15)) * RSTR_B + (lane >> 4) * 16);
    const uint32_t b_lm = (uint32_t)((wn + ((lane >> 4) & 1) * 8 + (lane & 7)) * RSTR_B
                                     + ((lane >> 3) & 1) * 16);

    float acc[4][4][4];
#pragma unroll
    for (int mf = 0; mf < 4; mf++)
#pragma unroll
        for (int nf = 0; nf < 4; nf++)
#pragma unroll
            for (int i = 0; i < 4; i++) acc[mf][nf][i] = 0.f;

    uint4 ra[4], rb[4];
#pragma unroll
    for (int l = 0; l < 4; l++) {
        ra[l] = *(const uint4*)(Ap + l * 32 * 1024);
        rb[l] = *(const uint4*)(Bp + l * 32 * 1024);
    }

    for (int it = 0; it < 16; it++) {
        const int buf = it & 1;
        const uint32_t abase = buf * (2 * TILE_B);
        const uint32_t bbase = abase + TILE_B;

#pragma unroll
        for (int l = 0; l < 4; l++) {
            *(uint4*)(smc + abase + s_off + l * 32 * RSTR_B) = ra[l];
            *(uint4*)(smc + bbase + s_off + l * 32 * RSTR_B) = rb[l];
        }
        __syncthreads();

        if (it + 1 < 16) {
            const size_t kofs = (size_t)(it + 1) * 64;
#pragma unroll
            for (int l = 0; l < 4; l++) {
                ra[l] = *(const uint4*)(Ap + l * 32 * 1024 + kofs);
                rb[l] = *(const uint4*)(Bp + l * 32 * 1024 + kofs);
            }
        }

        const uint32_t sA = sbase + abase + a_lm;
        const uint32_t sB = sbase + bbase + b_lm;
#pragma unroll
        for (int ks = 0; ks < 4; ks++) {
            uint32_t af[4][4], bb[2][4];
#pragma unroll
            for (int mf = 0; mf < 4; mf++)
                ldsm_x4(af[mf], sA + mf * 16 * RSTR_B + ks * 32);
#pragma unroll
            for (int np = 0; np < 2; np++)
                ldsm_x4(bb[np], sB + np * 16 * RSTR_B + ks * 32);
#pragma unroll
            for (int mf = 0; mf < 4; mf++) {
                mma16(acc[mf][0], af[mf], bb[0][0], bb[0][1]);
                mma16(acc[mf][1], af[mf], bb[0][2], bb[0][3]);
                mma16(acc[mf][2], af[mf], bb[1][0], bb[1][1]);
                mma16(acc[mf][3], af[mf], bb[1][2], bb[1][3]);
            }
        }
    }

#pragma unroll
    for (int nf = 0; nf < 4; nf++) {
        const int c = bn + wn + nf * 8 + 2 * qc;
        const float b0 = bias[c], b1 = bias[c + 1];
#pragma unroll
        for (int mf = 0; mf < 4; mf++) {
            const int rr = bm + wm + mf * 16 + qr;
            float2 v0 = make_float2(acc[mf][nf][0] + b0, acc[mf][nf][1] + b1);
            float2 v1 = make_float2(acc[mf][nf][2] + b0, acc[mf][nf][3] + b1);
            *(float2*)(C + (size_t)rr * N + c) = v0;
            *(float2*)(C + (size_t)(rr + 8) * N + c) = v1;
        }
    }
}

// ===========================================================================
// Fully fused two-layer pipelined GRU scan.
// R14: pass-1 (input-gate mma) software-pipelined OFF the serial chain:
// computed for step t+1 at the END of iteration t (after release; warps 1-7
// already run ahead). Results live in registers acc[6][4] across iterations.
// Layer-1 trails layer-0 by 2 steps so its pass-1 prefetch never blocks.
// Critical loop: wait -> stage h -> 32 pass-2 mma -> partials -> gates ->
// release.
// ===========================================================================
#define L0_CTAS 64
#define HROW 2064                 // smem row stride bytes (1032 bf16)
#define PSTRIDE 66                // part row stride floats
#define PBUF (8 * 16 * PSTRIDE)   // floats per part buffer (8448)
#define SM_HS    0                // 16 * 2064 = 33024
#define SM_WIH   33024            // 48 * 2064 = 99072
#define SM_PART  132096           // 2 * 33792 = 67584
#define SM_BI    199680           // 192
#define SM_BH    199872           // 192
#define SM_TOTAL 200064

__global__ void bar_reset() {
    for (int i = threadIdx.x; i < 128 * 32; i += blockDim.x) g_cntv[i] = 0u;
}

__global__ void __launch_bounds__(256, 1) scan_fused(
    const __nv_bfloat16* __restrict__ a16,
    const float* __restrict__ Wih0, const float* __restrict__ bih0,
    const float* __restrict__ Whh0, const float* __restrict__ bhh0,
    const float* __restrict__ Wih1, const float* __restrict__ bih1,
    const float* __restrict__ Whh1, const float* __restrict__ bhh1,
    __nv_bfloat16* __restrict__ h1, __nv_bfloat16* __restrict__ h2)
{
    extern __shared__ char dsm[];
    char*  hs   = dsm + SM_HS;
    char*  wih  = dsm + SM_WIH;
    float* part = (float*)(dsm + SM_PART);
    float* bi   = (float*)(dsm + SM_BI);
    float* bh   = (float*)(dsm + SM_BH);

    const int tid  = threadIdx.x;
    const int lane = tid & 31;
    const int warp = tid >> 5;
    const bool is_l1 = blockIdx.x >= L0_CTAS;
    const int jbase = (is_l1 ? (int)blockIdx.x - L0_CTAS : (int)blockIdx.x) * 16;

    unsigned* cnt_l0 = g_cntv;
    unsigned* cnt_l1 = g_cntv + 64 * 32;
    unsigned* my_cnt = g_cntv + (int)blockIdx.x * 32;
    unsigned* cnt_p1 = is_l1 ? cnt_l0 : (unsigned*)nullptr;
    unsigned* cnt_p2 = is_l1 ? cnt_l1 : cnt_l0;

    const __nv_bfloat16* xin   = is_l1 ? h1 : a16;
    const __nv_bfloat16* hprev = is_l1 ? h2 : h1;
    __nv_bfloat16*       hout  = is_l1 ? h2 : h1;

    // ---- One-time setup: W_ih rows (48) -> smem bf16 ----
    {
        const float* Wih = is_l1 ? Wih1 : Wih0;
        for (int f = tid; f < 48 * 256; f += 256) {
            int n = f >> 8, c4 = f & 255;
            int g = n >> 4, jj = n & 15;
            float4 v = *(const float4*)(Wih + (size_t)(g * 1024 + jbase + jj) * 1024 + c4 * 4);
            uint2 pk;
            pk.x = pk_bf16x2(v.x, v.y);
            pk.y = pk_bf16x2(v.z, v.w);
            *(uint2*)(wih + n * HROW + c4 * 8) = pk;
        }
    }
    if (tid < 48) {
        int g = tid >> 4, jj = tid & 15;
        bi[tid] = (is_l1 ? bih1 : bih0)[g * 1024 + jbase + jj];
        bh[tid] = (is_l1 ? bhh1 : bhh0)[g * 1024 + jbase + jj];
    }
    __syncthreads();

    // ---- W_hh fragments in registers (6 n-octets x 8 k-frags) ----
    uint32_t wf[6][8][2];
    {
        const float* W = is_l1 ? Whh1 : Whh0;
        const int nr = lane >> 2, kq2 = (lane & 3) * 2;
#pragma unroll
        for (int o = 0; o < 6; o++) {
            const float* wrow = W + (size_t)((o >> 1) * 1024 + jbase + (o & 1) * 8 + nr) * 1024
                              + warp * 128 + kq2;
#pragma unroll
            for (int kt = 0; kt < 8; kt++) {
                float2 lo = *(const float2*)(wrow + kt * 16);
                float2 hi = *(const float2*)(wrow + kt * 16 + 8);
                wf[o][kt][0] = pk_bf16x2(lo.x, lo.y);
                wf[o][kt][1] = pk_bf16x2(hi.x, hi.y);
            }
        }
    }

    const uint32_t hs_b   = smem_u32(hs);
    const uint32_t a_base = hs_b + (uint32_t)((lane & 15) * HROW + (lane >> 4) * 16 + warp * 256);
    const uint32_t wihb   = smem_u32(wih) + (uint32_t)(warp * 256
                           + (((lane >> 4) & 1) * 8 + (lane & 7)) * HROW
                           + ((lane >> 3) & 1) * 16);
    const int st_b0 = lane >> 4;
    const int st_c  = lane & 15;
    const int pslot = (warp * 8 + (lane & 7)) * 32;

    const int g_jj = tid & 15, g_b = tid >> 4;
    float hstate = 0.f;

    // Persistent pass-1 accumulators: [0..3] r/z (pass-2 accumulates on top),
    // [4..5] n_in (pass-2 never touches).
    float acc[6][4];

    // ---- pass-1 prologue for t = 0 ----
    if (is_l1) {
        if (lane < 8) {
            const unsigned* cp = cnt_p1 + pslot;
            while (ld_acq(cp) < 1u) { }
        }
        __syncwarp();
    }
#pragma unroll
    for (int l = 0; l < 8; l++) {
        int b = st_b0 + l * 2;
        uint4 v = __ldcg((const uint4*)(xin + ((size_t)(b << 10)) * 1024
                                        + warp * 128 + st_c * 8));
        *(uint4*)(hs + b * HROW + warp * 256 + st_c * 16) = v;
    }
    __syncwarp();
#pragma unroll
    for (int o = 0; o < 6; o++)
#pragma unroll
        for (int i = 0; i < 4; i++) acc[o][i] = 0.f;
#pragma unroll
    for (int kt = 0; kt < 8; kt++) {
        uint32_t a[4];
        ldsm_x4(a, a_base + kt * 32);
#pragma unroll
        for (int p = 0; p < 3; p++) {
            uint32_t bf[4];
            ldsm_x4(bf, wihb + p * 16 * HROW + kt * 32);
            mma16(acc[2 * p],     a, bf[0], bf[1]);
            mma16(acc[2 * p + 1], a, bf[2], bf[3]);
        }
    }

    for (int t = 0; t < TSEQ; t++) {
        float accN[2][4];
#pragma unroll
        for (int o = 0; o < 2; o++)
#pragma unroll
            for (int i = 0; i < 4; i++) accN[o][i] = 0.f;

        // ======== chain: pass-2 (h_{t-1} @ W_hh^T); skipped at t=0 ========
        if (t > 0) {
            if (lane < 8) {
                const unsigned* cp = cnt_p2 + pslot;
                while (ld_acq(cp) < (unsigned)t) { }
            }
            __syncwarp();
#pragma unroll
            for (int l = 0; l < 8; l++) {
                int b = st_b0 + l * 2;
                uint4 v = __ldcg((const uint4*)(hprev + ((size_t)((b << 10) + (t - 1))) * 1024
                                                + warp * 128 + st_c * 8));
                *(uint4*)(hs + b * HROW + warp * 256 + st_c * 16) = v;
            }
            __syncwarp();
#pragma unroll
            for (int kt = 0; kt < 8; kt++) {
                uint32_t a[4];
                ldsm_x4(a, a_base + kt * 32);
#pragma unroll
                for (int o = 0; o < 4; o++)
                    mma16(acc[o], a, wf[o][kt][0], wf[o][kt][1]);
                mma16(accN[0], a, wf[4][kt][0], wf[4][kt][1]);
                mma16(accN[1], a, wf[5][kt][0], wf[5][kt][1]);
            }
        }

        // partial store into buffer (t&1): [0:16) r, [16:32) z, [32:48) n_in, [48:64) n_rec
        float* pb = part + (t & 1) * PBUF;
        {
            float* pw = pb + warp * (16 * PSTRIDE);
            const int r = lane >> 2, c2 = (lane & 3) * 2;
#pragma unroll
            for (int o = 0; o < 6; o++) {
                *(float2*)(pw + r * PSTRIDE + o * 8 + c2)       = make_float2(acc[o][0], acc[o][1]);
                *(float2*)(pw + (r + 8) * PSTRIDE + o * 8 + c2) = make_float2(acc[o][2], acc[o][3]);
            }
#pragma unroll
            for (int o = 0; o < 2; o++) {
                *(float2*)(pw + r * PSTRIDE + 48 + o * 8 + c2)       = make_float2(accN[o][0], accN[o][1]);
                *(float2*)(pw + (r + 8) * PSTRIDE + 48 + o * 8 + c2) = make_float2(accN[o][2], accN[o][3]);
            }
        }
        __syncthreads();

        // ======== gates (fast math; register h state) ========
        {
            float sr = bi[g_jj] + bh[g_jj];
            float sz = bi[16 + g_jj] + bh[16 + g_jj];
            float xn = bi[32 + g_jj];
            float hn = bh[32 + g_jj];
#pragma unroll
            for (int w = 0; w < 8; w++) {
                const float* p = pb + w * (16 * PSTRIDE) + g_b * PSTRIDE;
                sr += p[g_jj]; sz += p[16 + g_jj]; xn += p[32 + g_jj]; hn += p[48 + g_jj];
            }
            float rg = fast_sigmoid(sr);
            float zg = fast_sigmoid(sz);
            float ng = fast_tanh(xn + rg * hn);
            hstate = (1.f - zg) * ng + zg * hstate;
            __stcg(hout + ((size_t)((g_b << 10) + t)) * 1024 + jbase + g_jj,
                   __float2bfloat16(hstate));
        }

        // ======== tail barrier: warps 1-7 run ahead; warp 0 releases ========
        if (warp == 0) {
            asm volatile("bar.sync 1, 256;" ::: "memory");
            if (lane == 0) st_rel(my_cnt, (unsigned)(t + 1));
        } else {
            asm volatile("bar.arrive 1, 256;" ::: "memory");
        }

        // ======== off-chain: pass-1 for t+1 ========
        if (t + 1 < TSEQ) {
            if (is_l1) {
                if (lane < 8) {
                    const unsigned* cp = cnt_p1 + pslot;
                    while (ld_acq(cp) < (unsigned)(t + 2)) { }
                }
                __syncwarp();
            }
#pragma unroll
            for (int l = 0; l < 8; l++) {
                int b = st_b0 + l * 2;
                uint4 v = __ldcg((const uint4*)(xin + ((size_t)((b << 10) + (t + 1))) * 1024
                                                + warp * 128 + st_c * 8));
                *(uint4*)(hs + b * HROW + warp * 256 + st_c * 16) = v;
            }
            __syncwarp();
#pragma unroll
            for (int o = 0; o < 6; o++)
#pragma unroll
                for (int i = 0; i < 4; i++) acc[o][i] = 0.f;
#pragma unroll
            for (int kt = 0; kt < 8; kt++) {
                uint32_t a[4];
                ldsm_x4(a, a_base + kt * 32);
#pragma unroll
                for (int p = 0; p < 3; p++) {
                    uint32_t bf[4];
                    ldsm_x4(bf, wihb + p * 16 * HROW + kt * 32);
                    mma16(acc[2 * p],     a, bf[0], bf[1]);
                    mma16(acc[2 * p + 1], a, bf[2], bf[3]);
                }
            }
        }
    }
}

// ===========================================================================
// log_softmax over axis=1 (T)
// ===========================================================================
__global__ void __launch_bounds__(1024) lse_kernel(
    const float* __restrict__ logits, float* __restrict__ lse)
{
    __shared__ float sm_m[1024], sm_s[1024];
    const int b = blockIdx.x;
    const int tid = threadIdx.x;
    const int c = tid & 127, ts = tid >> 7;
    const float* p = logits + ((size_t)((b << 10) + (ts << 7))) * NCLS + c;
    float m = -1e30f, s = 0.f;
    for (int i = 0; i < 128; i++) {
        float x = p[(size_t)i * NCLS];
        if (x > m) { s = s * expf(m - x) + 1.f; m = x; }
        else       { s += expf(x - m); }
    }
    sm_m[tid] = m; sm_s[tid] = s;
    __syncthreads();
    if (tid < 128) {
        float M = sm_m[tid], S = sm_s[tid];
#pragma unroll
        for (int k = 1; k < 8; k++) {
            float m2 = sm_m[tid + k * 128], s2 = sm_s[tid + k * 128];
            if (m2 > M) { S = S * expf(M - m2) + s2; M = m2; }
            else        { S += s2 * expf(m2 - M); }
        }
        lse[b * NCLS + tid] = M + logf(S);
    }
}

__global__ void sub_kernel(float* __restrict__ out, const float* __restrict__ lse)
{
    int idx = blockIdx.x * blockDim.x + threadIdx.x;
    int b = idx >> 17;
    int c = idx & 127;
    out[idx] -= lse[(b << 7) + c];
}

// ===========================================================================
extern "C" void kernel_launch(void* const* d_in, const int* in_sizes, int n_in,
                              void* d_out, int out_size)
{
    (void)in_sizes; (void)n_in; (void)out_size;
    const int*   tok  = (const int*)d_in[0];
    const float* emb  = (const float*)d_in[1];
    const float* Wih0 = (const float*)d_in[2];
    const float* Whh0 = (const float*)d_in[3];
    const float* bih0 = (const float*)d_in[4];
    const float* bhh0 = (const float*)d_in[5];
    const float* Wih1 = (const float*)d_in[6];
    const float* Whh1 = (const float*)d_in[7];
    const float* bih1 = (const float*)d_in[8];
    const float* bhh1 = (const float*)d_in[9];
    const float* Wlin = (const float*)d_in[10];
    const float* blin = (const float*)d_in[11];
    float* out = (float*)d_out;

    float *lseb;
    __nv_bfloat16 *h1, *h2, *a16, *b16;
    cudaGetSymbolAddress((void**)&lseb, g_lse);
    cudaGetSymbolAddress((void**)&h1,   g_h1);
    cudaGetSymbolAddress((void**)&h2,   g_h2);
    cudaGetSymbolAddress((void**)&a16,  g_a16);
    cudaGetSymbolAddress((void**)&b16,  g_b16);

    cudaFuncSetAttribute(gemm_bf16, cudaFuncAttributeMaxDynamicSharedMemorySize,
                         GEMM_SMEM_BYTES);
    cudaFuncSetAttribute(scan_fused, cudaFuncAttributeMaxDynamicSharedMemorySize,
                         SM_TOTAL);

    const size_t a_tot4 = ((size_t)MTOT * HD) / 4;
    const size_t l_tot4 = ((size_t)NCLS * HD) / 4;
    const int CB = 256;

    // Prologue
    conv_bf16<<<(unsigned)((a_tot4 + CB - 1) / CB), CB>>>(emb, tok, a16, a_tot4);
    conv_bf16<<<(unsigned)((l_tot4 + CB - 1) / CB), CB>>>(Wlin, nullptr, b16, l_tot4);
    bar_reset<<<1, 256>>>();

    // Fused two-layer scan
    scan_fused<<<128, 256, SM_TOTAL>>>(a16, Wih0, bih0, Whh0, bhh0,
                                       Wih1, bih1, Whh1, bhh1, h1, h2);

    // Head
    dim3 gL(MTOT / 128, 1);
    gemm_bf16<<<gL, 256, GEMM_SMEM_BYTES>>>(h2, b16, blin, out, NCLS);

    // log_softmax over T
    lse_kernel<<<BATCH, 1024>>>(out, lseb);
    sub_kernel<<<(MTOT * NCLS) / 1024, 1024>>>(out, lseb);
}

// round 15
// speedup vs baseline: 1.0936x; 1.0936x over previous
#include <cuda_runtime.h>
#include <cuda_bf16.h>
#include <cstdint>
#include <math.h>

#define BATCH 16
#define TSEQ  1024
#define HD    1024
#define MTOT  (BATCH * TSEQ)   // 16384
#define G3H   (3 * HD)         // 3072
#define NCLS  128

__device__ __nv_bfloat16 g_h1[(size_t)MTOT * HD];    // layer-0 hidden seq
__device__ __nv_bfloat16 g_h2[(size_t)MTOT * HD];    // layer-1 hidden seq
__device__ __nv_bfloat16 g_a16[(size_t)MTOT * HD];   // gathered emb (bf16)
__device__ __nv_bfloat16 g_b16[(size_t)G3H * HD];    // head weights bf16
__device__ float g_lse[BATCH * NCLS];
__device__ unsigned g_cntv[128 * 32];                // per-CTA step counters (128B stride)

// ===========================================================================
// fp32 -> bf16 convert (optionally gathering rows via tok); rows are K=1024
// ===========================================================================
__global__ void __launch_bounds__(256) conv_bf16(
    const float* __restrict__ in, const int* __restrict__ tok,
    __nv_bfloat16* __restrict__ out, size_t total4)
{
    size_t idx = (size_t)blockIdx.x * blockDim.x + threadIdx.x;
    if (idx >= total4) return;
    size_t e = idx << 2;
    size_t m = e >> 10;
    int    k = (int)(e & 1023);
    size_t srow = tok ? (size_t)tok[m] : m;
    float4 v = *(const float4*)(in + srow * 1024 + k);
    __nv_bfloat162 p0 = __floats2bfloat162_rn(v.x, v.y);
    __nv_bfloat162 p1 = __floats2bfloat162_rn(v.z, v.w);
    *(__nv_bfloat162*)(out + e)     = p0;
    *(__nv_bfloat162*)(out + e + 2) = p1;
}

// ===========================================================================
// Shared helpers
// ===========================================================================
__device__ __forceinline__ uint32_t smem_u32(const void* p) {
    uint32_t a;
    asm("{ .reg .u64 t; cvta.to.shared.u64 t, %1; cvt.u32.u64 %0, t; }"
        : "=r"(a) : "l"(p));
    return a;
}

__device__ __forceinline__ void ldsm_x4(uint32_t* r, uint32_t addr) {
    asm volatile("ldmatrix.sync.aligned.m8n8.x4.shared.b16 {%0,%1,%2,%3}, [%4];"
                 : "=r"(r[0]), "=r"(r[1]), "=r"(r[2]), "=r"(r[3]) : "r"(addr));
}

__device__ __forceinline__ void mma16(float* d, const uint32_t* a, uint32_t b0, uint32_t b1) {
    asm volatile(
        "mma.sync.aligned.m16n8k16.row.col.f32.bf16.bf16.f32 "
        "{%0,%1,%2,%3}, {%4,%5,%6,%7}, {%8,%9}, {%0,%1,%2,%3};"
        : "+f"(d[0]), "+f"(d[1]), "+f"(d[2]), "+f"(d[3])
        : "r"(a[0]), "r"(a[1]), "r"(a[2]), "r"(a[3]), "r"(b0), "r"(b1));
}

__device__ __forceinline__ uint32_t pk_bf16x2(float lo, float hi) {
    __nv_bfloat162 p = __floats2bfloat162_rn(lo, hi);
    return *reinterpret_cast<uint32_t*>(&p);
}

__device__ __forceinline__ unsigned ld_acq(const unsigned* p) {
    unsigned v;
    asm volatile("ld.acquire.gpu.global.u32 %0, [%1];" : "=r"(v) : "l"(p) : "memory");
    return v;
}

__device__ __forceinline__ void st_rel(unsigned* p, unsigned v) {
    asm volatile("st.release.gpu.global.u32 [%0], %1;" :: "l"(p), "r"(v) : "memory");
}

__device__ __forceinline__ float fast_sigmoid(float x) {
    float e = __expf(fminf(fmaxf(-x, -80.f), 80.f));
    return __fdividef(1.f, 1.f + e);
}

__device__ __forceinline__ float fast_tanh(float x) {
    float u = __expf(fminf(fmaxf(-2.f * x, -80.f), 80.f));
    return __fdividef(1.f - u, 1.f + u);
}

// ===========================================================================
// bf16 mma.sync GEMM (validated R7) — head only
// ===========================================================================
#define RSTR_B 144
#define TILE_B (128 * RSTR_B)
#define GEMM_SMEM_BYTES (4 * TILE_B)

__global__ void __launch_bounds__(256) gemm_bf16(
    const __nv_bfloat16* __restrict__ A16,
    const __nv_bfloat16* __restrict__ B16,
    const float* __restrict__ bias,
    float* __restrict__ C, int N)
{
    extern __shared__ char smc[];
    const uint32_t sbase = smem_u32(smc);
    const int tid  = threadIdx.x;
    const int lane = tid & 31;
    const int warp = tid >> 5;
    const int bm = blockIdx.x * 128;
    const int bn = blockIdx.y * 128;
    const int wm = (warp & 1) * 64;
    const int wn = (warp >> 1) * 32;
    const int qr = lane >> 2;
    const int qc = lane & 3;

    const int r0 = tid >> 3;
    const int ch = tid & 7;
    const __nv_bfloat16* Ap = A16 + (size_t)(bm + r0) * 1024 + ch * 8;
    const __nv_bfloat16* Bp = B16 + (size_t)(bn + r0) * 1024 + ch * 8;
    const uint32_t s_off = (uint32_t)(r0 * RSTR_B + ch * 16);

    const uint32_t a_lm = (uint32_t)((wm + (lane & 15)) * RSTR_B + (lane >> 4) * 16);
    const uint32_t b_lm = (uint32_t)((wn + ((lane >> 4) & 1) * 8 + (lane & 7)) * RSTR_B
                                     + ((lane >> 3) & 1) * 16);

    float acc[4][4][4];
#pragma unroll
    for (int mf = 0; mf < 4; mf++)
#pragma unroll
        for (int nf = 0; nf < 4; nf++)
#pragma unroll
            for (int i = 0; i < 4; i++) acc[mf][nf][i] = 0.f;

    uint4 ra[4], rb[4];
#pragma unroll
    for (int l = 0; l < 4; l++) {
        ra[l] = *(const uint4*)(Ap + l * 32 * 1024);
        rb[l] = *(const uint4*)(Bp + l * 32 * 1024);
    }

    for (int it = 0; it < 16; it++) {
        const int buf = it & 1;
        const uint32_t abase = buf * (2 * TILE_B);
        const uint32_t bbase = abase + TILE_B;

#pragma unroll
        for (int l = 0; l < 4; l++) {
            *(uint4*)(smc + abase + s_off + l * 32 * RSTR_B) = ra[l];
            *(uint4*)(smc + bbase + s_off + l * 32 * RSTR_B) = rb[l];
        }
        __syncthreads();

        if (it + 1 < 16) {
            const size_t kofs = (size_t)(it + 1) * 64;
#pragma unroll
            for (int l = 0; l < 4; l++) {
                ra[l] = *(const uint4*)(Ap + l * 32 * 1024 + kofs);
                rb[l] = *(const uint4*)(Bp + l * 32 * 1024 + kofs);
            }
        }

        const uint32_t sA = sbase + abase + a_lm;
        const uint32_t sB = sbase + bbase + b_lm;
#pragma unroll
        for (int ks = 0; ks < 4; ks++) {
            uint32_t af[4][4], bb[2][4];
#pragma unroll
            for (int mf = 0; mf < 4; mf++)
                ldsm_x4(af[mf], sA + mf * 16 * RSTR_B + ks * 32);
#pragma unroll
            for (int np = 0; np < 2; np++)
                ldsm_x4(bb[np], sB + np * 16 * RSTR_B + ks * 32);
#pragma unroll
            for (int mf = 0; mf < 4; mf++) {
                mma16(acc[mf][0], af[mf], bb[0][0], bb[0][1]);
                mma16(acc[mf][1], af[mf], bb[0][2], bb[0][3]);
                mma16(acc[mf][2], af[mf], bb[1][0], bb[1][1]);
                mma16(acc[mf][3], af[mf], bb[1][2], bb[1][3]);
            }
        }
    }

#pragma unroll
    for (int nf = 0; nf < 4; nf++) {
        const int c = bn + wn + nf * 8 + 2 * qc;
        const float b0 = bias[c], b1 = bias[c + 1];
#pragma unroll
        for (int mf = 0; mf < 4; mf++) {
            const int rr = bm + wm + mf * 16 + qr;
            float2 v0 = make_float2(acc[mf][nf][0] + b0, acc[mf][nf][1] + b1);
            float2 v1 = make_float2(acc[mf][nf][2] + b0, acc[mf][nf][3] + b1);
            *(float2*)(C + (size_t)rr * N + c) = v0;
            *(float2*)(C + (size_t)(rr + 8) * N + c) = v1;
        }
    }
}

// ===========================================================================
// Fully fused two-layer pipelined GRU scan (R13 ordering restored).
// R15: partials stored as [b][jj][4 gates] so gate threads read 2x LDS.64
// per warp block (conflict-free); bias sums hoisted out of the t-loop.
// ===========================================================================
#define L0_CTAS 64
#define HROW 2064                 // smem row stride bytes (1032 bf16)
#define PSTRIDE 66                // part row stride floats (b rows)
#define PBUF (8 * 16 * PSTRIDE)   // floats per part buffer (8448)
#define SM_HS    0                // 16 * 2064 = 33024
#define SM_WIH   33024            // 48 * 2064 = 99072
#define SM_PART  132096           // 2 * 33792 = 67584
#define SM_BI    199680           // 192
#define SM_BH    199872           // 192
#define SM_TOTAL 200064

__global__ void bar_reset() {
    for (int i = threadIdx.x; i < 128 * 32; i += blockDim.x) g_cntv[i] = 0u;
}

__global__ void __launch_bounds__(256, 1) scan_fused(
    const __nv_bfloat16* __restrict__ a16,
    const float* __restrict__ Wih0, const float* __restrict__ bih0,
    const float* __restrict__ Whh0, const float* __restrict__ bhh0,
    const float* __restrict__ Wih1, const float* __restrict__ bih1,
    const float* __restrict__ Whh1, const float* __restrict__ bhh1,
    __nv_bfloat16* __restrict__ h1, __nv_bfloat16* __restrict__ h2)
{
    extern __shared__ char dsm[];
    char*  hs   = dsm + SM_HS;
    char*  wih  = dsm + SM_WIH;
    float* part = (float*)(dsm + SM_PART);
    float* bi   = (float*)(dsm + SM_BI);
    float* bh   = (float*)(dsm + SM_BH);

    const int tid  = threadIdx.x;
    const int lane = tid & 31;
    const int warp = tid >> 5;
    const bool is_l1 = blockIdx.x >= L0_CTAS;
    const int jbase = (is_l1 ? (int)blockIdx.x - L0_CTAS : (int)blockIdx.x) * 16;

    unsigned* cnt_l0 = g_cntv;
    unsigned* cnt_l1 = g_cntv + 64 * 32;
    unsigned* my_cnt = g_cntv + (int)blockIdx.x * 32;
    unsigned* cnt_p1 = is_l1 ? cnt_l0 : (unsigned*)nullptr;
    unsigned* cnt_p2 = is_l1 ? cnt_l1 : cnt_l0;

    const __nv_bfloat16* xin   = is_l1 ? h1 : a16;
    const __nv_bfloat16* hprev = is_l1 ? h2 : h1;
    __nv_bfloat16*       hout  = is_l1 ? h2 : h1;

    // ---- One-time setup: W_ih rows (48) -> smem bf16 ----
    {
        const float* Wih = is_l1 ? Wih1 : Wih0;
        for (int f = tid; f < 48 * 256; f += 256) {
            int n = f >> 8, c4 = f & 255;
            int g = n >> 4, jj = n & 15;
            float4 v = *(const float4*)(Wih + (size_t)(g * 1024 + jbase + jj) * 1024 + c4 * 4);
            uint2 pk;
            pk.x = pk_bf16x2(v.x, v.y);
            pk.y = pk_bf16x2(v.z, v.w);
            *(uint2*)(wih + n * HROW + c4 * 8) = pk;
        }
    }
    if (tid < 48) {
        int g = tid >> 4, jj = tid & 15;
        bi[tid] = (is_l1 ? bih1 : bih0)[g * 1024 + jbase + jj];
        bh[tid] = (is_l1 ? bhh1 : bhh0)[g * 1024 + jbase + jj];
    }
    __syncthreads();

    // ---- W_hh fragments in registers (6 n-octets x 8 k-frags) ----
    uint32_t wf[6][8][2];
    {
        const float* W = is_l1 ? Whh1 : Whh0;
        const int nr = lane >> 2, kq2 = (lane & 3) * 2;
#pragma unroll
        for (int o = 0; o < 6; o++) {
            const float* wrow = W + (size_t)((o >> 1) * 1024 + jbase + (o & 1) * 8 + nr) * 1024
                              + warp * 128 + kq2;
#pragma unroll
            for (int kt = 0; kt < 8; kt++) {
                float2 lo = *(const float2*)(wrow + kt * 16);
                float2 hi = *(const float2*)(wrow + kt * 16 + 8);
                wf[o][kt][0] = pk_bf16x2(lo.x, lo.y);
                wf[o][kt][1] = pk_bf16x2(hi.x, hi.y);
            }
        }
    }

    const uint32_t hs_b   = smem_u32(hs);
    const uint32_t a_base = hs_b + (uint32_t)((lane & 15) * HROW + (lane >> 4) * 16 + warp * 256);
    const uint32_t wihb   = smem_u32(wih) + (uint32_t)(warp * 256
                           + (((lane >> 4) & 1) * 8 + (lane & 7)) * HROW
                           + ((lane >> 3) & 1) * 16);
    const int st_b0 = lane >> 4;
    const int st_c  = lane & 15;
    const int pslot = (warp * 8 + (lane & 7)) * 32;

    const int g_jj = tid & 15, g_b = tid >> 4;
    float hstate = 0.f;

    // Hoisted per-thread gate constants (bias sums)
    const float c_r  = bi[g_jj] + bh[g_jj];
    const float c_z  = bi[16 + g_jj] + bh[16 + g_jj];
    const float c_xn = bi[32 + g_jj];
    const float c_hn = bh[32 + g_jj];

    for (int t = 0; t < TSEQ; t++) {
        // ======== pass 1: input gates (x_t @ W_ih^T) ========
        if (is_l1) {
            if (lane < 8) {
                const unsigned* cp = cnt_p1 + pslot;
                while (ld_acq(cp) < (unsigned)(t + 1)) { }
            }
            __syncwarp();
        }
#pragma unroll
        for (int l = 0; l < 8; l++) {
            int b = st_b0 + l * 2;
            uint4 v = __ldcg((const uint4*)(xin + ((size_t)((b << 10) + t)) * 1024
                                            + warp * 128 + st_c * 8));
            *(uint4*)(hs + b * HROW + warp * 256 + st_c * 16) = v;
        }
        __syncwarp();

        float acc[6][4], accN[2][4];
#pragma unroll
        for (int o = 0; o < 6; o++)
#pragma unroll
            for (int i = 0; i < 4; i++) acc[o][i] = 0.f;
#pragma unroll
        for (int o = 0; o < 2; o++)
#pragma unroll
            for (int i = 0; i < 4; i++) accN[o][i] = 0.f;

#pragma unroll
        for (int kt = 0; kt < 8; kt++) {
            uint32_t a[4];
            ldsm_x4(a, a_base + kt * 32);
#pragma unroll
            for (int p = 0; p < 3; p++) {
                uint32_t bf[4];
                ldsm_x4(bf, wihb + p * 16 * HROW + kt * 32);
                mma16(acc[2 * p],     a, bf[0], bf[1]);
                mma16(acc[2 * p + 1], a, bf[2], bf[3]);
            }
        }

        // ======== pass 2: recurrent gates (h_{t-1} @ W_hh^T) ========
        if (t > 0) {
            if (lane < 8) {
                const unsigned* cp = cnt_p2 + pslot;
                while (ld_acq(cp) < (unsigned)t) { }
            }
            __syncwarp();
#pragma unroll
            for (int l = 0; l < 8; l++) {
                int b = st_b0 + l * 2;
                uint4 v = __ldcg((const uint4*)(hprev + ((size_t)((b << 10) + (t - 1))) * 1024
                                                + warp * 128 + st_c * 8));
                *(uint4*)(hs + b * HROW + warp * 256 + st_c * 16) = v;
            }
        } else {
#pragma unroll
            for (int l = 0; l < 8; l++) {
                int b = st_b0 + l * 2;
                *(uint4*)(hs + b * HROW + warp * 256 + st_c * 16) = make_uint4(0, 0, 0, 0);
            }
        }
        __syncwarp();

#pragma unroll
        for (int kt = 0; kt < 8; kt++) {
            uint32_t a[4];
            ldsm_x4(a, a_base + kt * 32);
#pragma unroll
            for (int o = 0; o < 4; o++)
                mma16(acc[o], a, wf[o][kt][0], wf[o][kt][1]);
            mma16(accN[0], a, wf[4][kt][0], wf[4][kt][1]);
            mma16(accN[1], a, wf[5][kt][0], wf[5][kt][1]);
        }

        // partial store into buffer (t&1): layout [b][jj][gate]
        //   gate 0=r, 1=z, 2=n_in, 3=n_rec; addr = b*66 + jj*4 + gate
        float* pb = part + (t & 1) * PBUF;
        {
            float* pw = pb + warp * (16 * PSTRIDE);
            const int r = lane >> 2, c2 = (lane & 3) * 2;
#pragma unroll
            for (int o = 0; o < 6; o++) {
                const int g = o >> 1;
                const int j0 = (o & 1) * 8 + c2;
                pw[r * PSTRIDE + j0 * 4 + g]             = acc[o][0];
                pw[r * PSTRIDE + (j0 + 1) * 4 + g]       = acc[o][1];
                pw[(r + 8) * PSTRIDE + j0 * 4 + g]       = acc[o][2];
                pw[(r + 8) * PSTRIDE + (j0 + 1) * 4 + g] = acc[o][3];
            }
#pragma unroll
            for (int o = 0; o < 2; o++) {
                const int j0 = o * 8 + c2;
                pw[r * PSTRIDE + j0 * 4 + 3]             = accN[o][0];
                pw[r * PSTRIDE + (j0 + 1) * 4 + 3]       = accN[o][1];
                pw[(r + 8) * PSTRIDE + j0 * 4 + 3]       = accN[o][2];
                pw[(r + 8) * PSTRIDE + (j0 + 1) * 4 + 3] = accN[o][3];
            }
        }
        __syncthreads();

        // ======== gates (fast math; register h state; LDS.64 reduce) ========
        {
            float sr = c_r, sz = c_z, xn = c_xn, hn = c_hn;
#pragma unroll
            for (int w = 0; w < 8; w++) {
                const float* p = pb + w * (16 * PSTRIDE) + g_b * PSTRIDE + g_jj * 4;
                float2 v01 = *(const float2*)p;         // r, z
                float2 v23 = *(const float2*)(p + 2);   // n_in, n_rec
                sr += v01.x; sz += v01.y; xn += v23.x; hn += v23.y;
            }
            float rg = fast_sigmoid(sr);
            float zg = fast_sigmoid(sz);
            float ng = fast_tanh(xn + rg * hn);
            hstate = (1.f - zg) * ng + zg * hstate;
            __stcg(hout + ((size_t)((g_b << 10) + t)) * 1024 + jbase + g_jj,
                   __float2bfloat16(hstate));
        }

        // ======== tail barrier: warps 1-7 run ahead; warp 0 releases ========
        if (warp == 0) {
            asm volatile("bar.sync 1, 256;" ::: "memory");
            if (lane == 0) st_rel(my_cnt, (unsigned)(t + 1));
        } else {
            asm volatile("bar.arrive 1, 256;" ::: "memory");
        }
    }
}

// ===========================================================================
// log_softmax over axis=1 (T)
// ===========================================================================
__global__ void __launch_bounds__(1024) lse_kernel(
    const float* __restrict__ logits, float* __restrict__ lse)
{
    __shared__ float sm_m[1024], sm_s[1024];
    const int b = blockIdx.x;
    const int tid = threadIdx.x;
    const int c = tid & 127, ts = tid >> 7;
    const float* p = logits + ((size_t)((b << 10) + (ts << 7))) * NCLS + c;
    float m = -1e30f, s = 0.f;
    for (int i = 0; i < 128; i++) {
        float x = p[(size_t)i * NCLS];
        if (x > m) { s = s * expf(m - x) + 1.f; m = x; }
        else       { s += expf(x - m); }
    }
    sm_m[tid] = m; sm_s[tid] = s;
    __syncthreads();
    if (tid < 128) {
        float M = sm_m[tid], S = sm_s[tid];
#pragma unroll
        for (int k = 1; k < 8; k++) {
            float m2 = sm_m[tid + k * 128], s2 = sm_s[tid + k * 128];
            if (m2 > M) { S = S * expf(M - m2) + s2; M = m2; }
            else        { S += s2 * expf(m2 - M); }
        }
        lse[b * NCLS + tid] = M + logf(S);
    }
}

__global__ void sub_kernel(float* __restrict__ out, const float* __restrict__ lse)
{
    int idx = blockIdx.x * blockDim.x + threadIdx.x;
    int b = idx >> 17;
    int c = idx & 127;
    out[idx] -= lse[(b << 7) + c];
}

// ===========================================================================
extern "C" void kernel_launch(void* const* d_in, const int* in_sizes, int n_in,
                              void* d_out, int out_size)
{
    (void)in_sizes; (void)n_in; (void)out_size;
    const int*   tok  = (const int*)d_in[0];
    const float* emb  = (const float*)d_in[1];
    const float* Wih0 = (const float*)d_in[2];
    const float* Whh0 = (const float*)d_in[3];
    const float* bih0 = (const float*)d_in[4];
    const float* bhh0 = (const float*)d_in[5];
    const float* Wih1 = (const float*)d_in[6];
    const float* Whh1 = (const float*)d_in[7];
    const float* bih1 = (const float*)d_in[8];
    const float* bhh1 = (const float*)d_in[9];
    const float* Wlin = (const float*)d_in[10];
    const float* blin = (const float*)d_in[11];
    float* out = (float*)d_out;

    float *lseb;
    __nv_bfloat16 *h1, *h2, *a16, *b16;
    cudaGetSymbolAddress((void**)&lseb, g_lse);
    cudaGetSymbolAddress((void**)&h1,   g_h1);
    cudaGetSymbolAddress((void**)&h2,   g_h2);
    cudaGetSymbolAddress((void**)&a16,  g_a16);
    cudaGetSymbolAddress((void**)&b16,  g_b16);

    cudaFuncSetAttribute(gemm_bf16, cudaFuncAttributeMaxDynamicSharedMemorySize,
                         GEMM_SMEM_BYTES);
    cudaFuncSetAttribute(scan_fused, cudaFuncAttributeMaxDynamicSharedMemorySize,
                         SM_TOTAL);

    const size_t a_tot4 = ((size_t)MTOT * HD) / 4;
    const size_t l_tot4 = ((size_t)NCLS * HD) / 4;
    const int CB = 256;

    // Prologue
    conv_bf16<<<(unsigned)((a_tot4 + CB - 1) / CB), CB>>>(emb, tok, a16, a_tot4);
    conv_bf16<<<(unsigned)((l_tot4 + CB - 1) / CB), CB>>>(Wlin, nullptr, b16, l_tot4);
    bar_reset<<<1, 256>>>();

    // Fused two-layer scan
    scan_fused<<<128, 256, SM_TOTAL>>>(a16, Wih0, bih0, Whh0, bhh0,
                                       Wih1, bih1, Whh1, bhh1, h1, h2);

    // Head
    dim3 gL(MTOT / 128, 1);
    gemm_bf16<<<gL, 256, GEMM_SMEM_BYTES>>>(h2, b16, blin, out, NCLS);

    // log_softmax over T
    lse_kernel<<<BATCH, 1024>>>(out, lseb);
    sub_kernel<<<(MTOT * NCLS) / 1024, 1024>>>(out, lseb);
}

// round 16
// speedup vs baseline: 1.1830x; 1.0818x over previous
#include <cuda_runtime.h>
#include <cuda_bf16.h>
#include <cstdint>
#include <math.h>

#define BATCH 16
#define TSEQ  1024
#define HD    1024
#define MTOT  (BATCH * TSEQ)   // 16384
#define G3H   (3 * HD)         // 3072
#define NCLS  128

// Fragment-order buffers: [t][w:8][kt:8][lane:32] x 16B  (32KB per t)
__device__ __nv_bfloat16 g_a16f[(size_t)MTOT * HD];  // emb fragments
__device__ __nv_bfloat16 g_h1f[(size_t)MTOT * HD];   // layer-0 h fragments
__device__ __nv_bfloat16 g_h2f[(size_t)MTOT * HD];   // layer-1 h fragments
__device__ __nv_bfloat16 g_h2r[(size_t)MTOT * HD];   // layer-1 h row-major (head input)
__device__ __nv_bfloat16 g_b16[(size_t)G3H * HD];    // head weights bf16
__device__ float g_lse[BATCH * NCLS];
__device__ unsigned g_cntv[128 * 32];                // per-CTA step counters (128B stride)

// ===========================================================================
// Helpers
// ===========================================================================
__device__ __forceinline__ uint32_t smem_u32(const void* p) {
    uint32_t a;
    asm("{ .reg .u64 t; cvta.to.shared.u64 t, %1; cvt.u32.u64 %0, t; }"
        : "=r"(a) : "l"(p));
    return a;
}

__device__ __forceinline__ void ldsm_x4(uint32_t* r, uint32_t addr) {
    asm volatile("ldmatrix.sync.aligned.m8n8.x4.shared.b16 {%0,%1,%2,%3}, [%4];"
                 : "=r"(r[0]), "=r"(r[1]), "=r"(r[2]), "=r"(r[3]) : "r"(addr));
}

__device__ __forceinline__ void mma16(float* d, const uint32_t* a, uint32_t b0, uint32_t b1) {
    asm volatile(
        "mma.sync.aligned.m16n8k16.row.col.f32.bf16.bf16.f32 "
        "{%0,%1,%2,%3}, {%4,%5,%6,%7}, {%8,%9}, {%0,%1,%2,%3};"
        : "+f"(d[0]), "+f"(d[1]), "+f"(d[2]), "+f"(d[3])
        : "r"(a[0]), "r"(a[1]), "r"(a[2]), "r"(a[3]), "r"(b0), "r"(b1));
}

__device__ __forceinline__ uint32_t pk_bf16x2(float lo, float hi) {
    __nv_bfloat162 p = __floats2bfloat162_rn(lo, hi);
    return *reinterpret_cast<uint32_t*>(&p);
}

__device__ __forceinline__ unsigned ld_acq(const unsigned* p) {
    unsigned v;
    asm volatile("ld.acquire.gpu.global.u32 %0, [%1];" : "=r"(v) : "l"(p) : "memory");
    return v;
}

__device__ __forceinline__ void st_rel(unsigned* p, unsigned v) {
    asm volatile("st.release.gpu.global.u32 [%0], %1;" :: "l"(p), "r"(v) : "memory");
}

__device__ __forceinline__ float fast_sigmoid(float x) {
    float e = __expf(fminf(fmaxf(-x, -80.f), 80.f));
    return __fdividef(1.f, 1.f + e);
}

__device__ __forceinline__ float fast_tanh(float x) {
    float u = __expf(fminf(fmaxf(-2.f * x, -80.f), 80.f));
    return __fdividef(1.f - u, 1.f + u);
}

// ===========================================================================
// emb gather -> fragment-order bf16. One thread per 16B fragment.
// idx = ((t*8 + w)*8 + kt)*32 + lane
// ===========================================================================
__global__ void __launch_bounds__(256) conv_frag(
    const float* __restrict__ emb, const int* __restrict__ tok,
    __nv_bfloat16* __restrict__ outf)
{
    unsigned idx = blockIdx.x * 256u + threadIdx.x;   // < 2,097,152
    int lane = idx & 31;
    int kt   = (idx >> 5) & 7;
    int w    = (idx >> 8) & 7;
    int t    = idx >> 11;
    int qr = lane >> 2, qc = lane & 3;
    int kb = w * 128 + kt * 16;
    const float* r0 = emb + (size_t)tok[qr * 1024 + t] * 1024 + kb;
    const float* r1 = emb + (size_t)tok[(qr + 8) * 1024 + t] * 1024 + kb;
    float2 v0a = *(const float2*)(r0 + 2 * qc);
    float2 v0b = *(const float2*)(r0 + 8 + 2 * qc);
    float2 v1a = *(const float2*)(r1 + 2 * qc);
    float2 v1b = *(const float2*)(r1 + 8 + 2 * qc);
    uint4 f;
    f.x = pk_bf16x2(v0a.x, v0a.y);   // a0
    f.y = pk_bf16x2(v1a.x, v1a.y);   // a1
    f.z = pk_bf16x2(v0b.x, v0b.y);   // a2
    f.w = pk_bf16x2(v1b.x, v1b.y);   // a3
    ((uint4*)outf)[idx] = f;
}

// fp32 -> bf16 row-major convert (head weights)
__global__ void __launch_bounds__(256) conv_bf16(
    const float* __restrict__ in, __nv_bfloat16* __restrict__ out, size_t total4)
{
    size_t idx = (size_t)blockIdx.x * blockDim.x + threadIdx.x;
    if (idx >= total4) return;
    size_t e = idx << 2;
    float4 v = *(const float4*)(in + e);
    *(__nv_bfloat162*)(out + e)     = __floats2bfloat162_rn(v.x, v.y);
    *(__nv_bfloat162*)(out + e + 2) = __floats2bfloat162_rn(v.z, v.w);
}

// ===========================================================================
// bf16 mma.sync GEMM (validated R7) — head only
// ===========================================================================
#define RSTR_B 144
#define TILE_B (128 * RSTR_B)
#define GEMM_SMEM_BYTES (4 * TILE_B)

__global__ void __launch_bounds__(256) gemm_bf16(
    const __nv_bfloat16* __restrict__ A16,
    const __nv_bfloat16* __restrict__ B16,
    const float* __restrict__ bias,
    float* __restrict__ C, int N)
{
    extern __shared__ char smc[];
    const uint32_t sbase = smem_u32(smc);
    const int tid  = threadIdx.x;
    const int lane = tid & 31;
    const int warp = tid >> 5;
    const int bm = blockIdx.x * 128;
    const int bn = blockIdx.y * 128;
    const int wm = (warp & 1) * 64;
    const int wn = (warp >> 1) * 32;
    const int qr = lane >> 2;
    const int qc = lane & 3;

    const int r0 = tid >> 3;
    const int ch = tid & 7;
    const __nv_bfloat16* Ap = A16 + (size_t)(bm + r0) * 1024 + ch * 8;
    const __nv_bfloat16* Bp = B16 + (size_t)(bn + r0) * 1024 + ch * 8;
    const uint32_t s_off = (uint32_t)(r0 * RSTR_B + ch * 16);

    const uint32_t a_lm = (uint32_t)((wm + (lane & 15)) * RSTR_B + (lane >> 4) * 16);
    const uint32_t b_lm = (uint32_t)((wn + ((lane >> 4) & 1) * 8 + (lane & 7)) * RSTR_B
                                     + ((lane >> 3) & 1) * 16);

    float acc[4][4][4];
#pragma unroll
    for (int mf = 0; mf < 4; mf++)
#pragma unroll
        for (int nf = 0; nf < 4; nf++)
#pragma unroll
            for (int i = 0; i < 4; i++) acc[mf][nf][i] = 0.f;

    uint4 ra[4], rb[4];
#pragma unroll
    for (int l = 0; l < 4; l++) {
        ra[l] = *(const uint4*)(Ap + l * 32 * 1024);
        rb[l] = *(const uint4*)(Bp + l * 32 * 1024);
    }

    for (int it = 0; it < 16; it++) {
        const int buf = it & 1;
        const uint32_t abase = buf * (2 * TILE_B);
        const uint32_t bbase = abase + TILE_B;

#pragma unroll
        for (int l = 0; l < 4; l++) {
            *(uint4*)(smc + abase + s_off + l * 32 * RSTR_B) = ra[l];
            *(uint4*)(smc + bbase + s_off + l * 32 * RSTR_B) = rb[l];
        }
        __syncthreads();

        if (it + 1 < 16) {
            const size_t kofs = (size_t)(it + 1) * 64;
#pragma unroll
            for (int l = 0; l < 4; l++) {
                ra[l] = *(const uint4*)(Ap + l * 32 * 1024 + kofs);
                rb[l] = *(const uint4*)(Bp + l * 32 * 1024 + kofs);
            }
        }

        const uint32_t sA = sbase + abase + a_lm;
        const uint32_t sB = sbase + bbase + b_lm;
#pragma unroll
        for (int ks = 0; ks < 4; ks++) {
            uint32_t af[4][4], bb[2][4];
#pragma unroll
            for (int mf = 0; mf < 4; mf++)
                ldsm_x4(af[mf], sA + mf * 16 * RSTR_B + ks * 32);
#pragma unroll
            for (int np = 0; np < 2; np++)
                ldsm_x4(bb[np], sB + np * 16 * RSTR_B + ks * 32);
#pragma unroll
            for (int mf = 0; mf < 4; mf++) {
                mma16(acc[mf][0], af[mf], bb[0][0], bb[0][1]);
                mma16(acc[mf][1], af[mf], bb[0][2], bb[0][3]);
                mma16(acc[mf][2], af[mf], bb[1][0], bb[1][1]);
                mma16(acc[mf][3], af[mf], bb[1][2], bb[1][3]);
            }
        }
    }

#pragma unroll
    for (int nf = 0; nf < 4; nf++) {
        const int c = bn + wn + nf * 8 + 2 * qc;
        const float b0 = bias[c], b1 = bias[c + 1];
#pragma unroll
        for (int mf = 0; mf < 4; mf++) {
            const int rr = bm + wm + mf * 16 + qr;
            float2 v0 = make_float2(acc[mf][nf][0] + b0, acc[mf][nf][1] + b1);
            float2 v1 = make_float2(acc[mf][nf][2] + b0, acc[mf][nf][3] + b1);
            *(float2*)(C + (size_t)rr * N + c) = v0;
            *(float2*)(C + (size_t)(rr + 8) * N + c) = v1;
        }
    }
}

// ===========================================================================
// Fully fused two-layer pipelined GRU scan, fragment-direct A operands.
// h/x live in GLOBAL fragment order: consumers issue 8 coalesced LDG.128
// per warp per pass (no STS / no A-ldsm / no smem h staging).
// Producers write each h value at its fragment position (one 512B block
// per CTA-step). W_ih via smem ldsm; W_hh in registers (unchanged).
// ===========================================================================
#define L0_CTAS 64
#define HROW 2064                 // wih smem row stride bytes
#define PSTRIDE 66                // part row stride floats (b rows)
#define PBUF (8 * 16 * PSTRIDE)   // floats per part buffer (8448)
#define SM_WIH   0                // 48 * 2064 = 99072
#define SM_PART  99072            // 2 * 33792 = 67584
#define SM_BI    166656           // 192
#define SM_BH    166848           // 192
#define SM_TOTAL 167040

__global__ void bar_reset() {
    for (int i = threadIdx.x; i < 128 * 32; i += blockDim.x) g_cntv[i] = 0u;
}

__global__ void __launch_bounds__(256, 1) scan_fused(
    const __nv_bfloat16* __restrict__ a16f,
    const float* __restrict__ Wih0, const float* __restrict__ bih0,
    const float* __restrict__ Whh0, const float* __restrict__ bhh0,
    const float* __restrict__ Wih1, const float* __restrict__ bih1,
    const float* __restrict__ Whh1, const float* __restrict__ bhh1,
    __nv_bfloat16* __restrict__ h1f, __nv_bfloat16* __restrict__ h2f,
    __nv_bfloat16* __restrict__ h2r)
{
    extern __shared__ char dsm[];
    char*  wih  = dsm + SM_WIH;
    float* part = (float*)(dsm + SM_PART);
    float* bi   = (float*)(dsm + SM_BI);
    float* bh   = (float*)(dsm + SM_BH);

    const int tid  = threadIdx.x;
    const int lane = tid & 31;
    const int warp = tid >> 5;
    const bool is_l1 = blockIdx.x >= L0_CTAS;
    const int jbase = (is_l1 ? (int)blockIdx.x - L0_CTAS : (int)blockIdx.x) * 16;

    unsigned* cnt_l0 = g_cntv;
    unsigned* cnt_l1 = g_cntv + 64 * 32;
    unsigned* my_cnt = g_cntv + (int)blockIdx.x * 32;
    unsigned* cnt_p1 = is_l1 ? cnt_l0 : (unsigned*)nullptr;
    unsigned* cnt_p2 = is_l1 ? cnt_l1 : cnt_l0;

    const __nv_bfloat16* xinf   = is_l1 ? h1f : a16f;   // pass-1 fragments
    const __nv_bfloat16* hprevf = is_l1 ? h2f : h1f;    // pass-2 fragments
    __nv_bfloat16*       houtf  = is_l1 ? h2f : h1f;

    // ---- One-time setup: W_ih rows (48) -> smem bf16 ----
    {
        const float* Wih = is_l1 ? Wih1 : Wih0;
        for (int f = tid; f < 48 * 256; f += 256) {
            int n = f >> 8, c4 = f & 255;
            int g = n >> 4, jj = n & 15;
            float4 v = *(const float4*)(Wih + (size_t)(g * 1024 + jbase + jj) * 1024 + c4 * 4);
            uint2 pk;
            pk.x = pk_bf16x2(v.x, v.y);
            pk.y = pk_bf16x2(v.z, v.w);
            *(uint2*)(wih + n * HROW + c4 * 8) = pk;
        }
    }
    if (tid < 48) {
        int g = tid >> 4, jj = tid & 15;
        bi[tid] = (is_l1 ? bih1 : bih0)[g * 1024 + jbase + jj];
        bh[tid] = (is_l1 ? bhh1 : bhh0)[g * 1024 + jbase + jj];
    }
    __syncthreads();

    // ---- W_hh fragments in registers (6 n-octets x 8 k-frags) ----
    uint32_t wf[6][8][2];
    {
        const float* W = is_l1 ? Whh1 : Whh0;
        const int nr = lane >> 2, kq2 = (lane & 3) * 2;
#pragma unroll
        for (int o = 0; o < 6; o++) {
            const float* wrow = W + (size_t)((o >> 1) * 1024 + jbase + (o & 1) * 8 + nr) * 1024
                              + warp * 128 + kq2;
#pragma unroll
            for (int kt = 0; kt < 8; kt++) {
                float2 lo = *(const float2*)(wrow + kt * 16);
                float2 hi = *(const float2*)(wrow + kt * 16 + 8);
                wf[o][kt][0] = pk_bf16x2(lo.x, lo.y);
                wf[o][kt][1] = pk_bf16x2(hi.x, hi.y);
            }
        }
    }

    const uint32_t wihb = smem_u32(wih) + (uint32_t)(warp * 256
                         + (((lane >> 4) & 1) * 8 + (lane & 7)) * HROW
                         + ((lane >> 3) & 1) * 16);
    const int pslot = (warp * 8 + (lane & 7)) * 32;

    // Fragment LDG bases (uint4 units): [t][w][kt][lane]; +2048 per t
    const uint4* xw = (const uint4*)xinf   + warp * 256 + lane;
    const uint4* hw = (const uint4*)hprevf + warp * 256 + lane;

    // Gate-thread constants
    const int g_jj = tid & 15, g_b = tid >> 4;
    const float c_r  = bi[g_jj] + bh[g_jj];
    const float c_z  = bi[16 + g_jj] + bh[16 + g_jj];
    const float c_xn = bi[32 + g_jj];
    const float c_hn = bh[32 + g_jj];
    float hstate = 0.f;

    // Fragment write offset for this gate thread's (b, j) value
    uint32_t fr_off;
    {
        int koff = g_jj;                 // jbase is 16-aligned
        int aslot, pairi;
        if (koff < 8) { aslot = (g_b < 8) ? 0 : 1; pairi = koff >> 1; }
        else          { aslot = (g_b < 8) ? 2 : 3; pairi = (koff - 8) >> 1; }
        int lanep = (g_b & 7) * 4 + pairi;
        fr_off = (uint32_t)((jbase >> 4) * 512 + lanep * 16 + aslot * 4 + (koff & 1) * 2);
    }
    __nv_bfloat16* houtp = (__nv_bfloat16*)((char*)houtf + fr_off);

    for (int t = 0; t < TSEQ; t++) {
        // ======== pass 1: input gates (x_t @ W_ih^T) ========
        if (is_l1) {
            if (lane < 8) {
                const unsigned* cp = cnt_p1 + pslot;
                while (ld_acq(cp) < (unsigned)(t + 1)) { }
            }
            __syncwarp();
        }
        uint4 xf[8];
        {
            const uint4* xp = xw + (size_t)t * 2048;
#pragma unroll
            for (int kt = 0; kt < 8; kt++) xf[kt] = __ldcg(xp + kt * 32);
        }

        float acc[6][4], accN[2][4];
#pragma unroll
        for (int o = 0; o < 6; o++)
#pragma unroll
            for (int i = 0; i < 4; i++) acc[o][i] = 0.f;
#pragma unroll
        for (int o = 0; o < 2; o++)
#pragma unroll
            for (int i = 0; i < 4; i++) accN[o][i] = 0.f;

#pragma unroll
        for (int kt = 0; kt < 8; kt++) {
#pragma unroll
            for (int p = 0; p < 3; p++) {
                uint32_t bf[4];
                ldsm_x4(bf, wihb + p * 16 * HROW + kt * 32);
                mma16(acc[2 * p],     (const uint32_t*)&xf[kt], bf[0], bf[1]);
                mma16(acc[2 * p + 1], (const uint32_t*)&xf[kt], bf[2], bf[3]);
            }
        }

        // ======== pass 2: recurrent gates (h_{t-1} @ W_hh^T) ========
        if (t > 0) {
            if (lane < 8) {
                const unsigned* cp = cnt_p2 + pslot;
                while (ld_acq(cp) < (unsigned)t) { }
            }
            __syncwarp();
            uint4 hf[8];
            const uint4* hp = hw + (size_t)(t - 1) * 2048;
#pragma unroll
            for (int kt = 0; kt < 8; kt++) hf[kt] = __ldcg(hp + kt * 32);
#pragma unroll
            for (int kt = 0; kt < 8; kt++) {
#pragma unroll
                for (int o = 0; o < 4; o++)
                    mma16(acc[o], (const uint32_t*)&hf[kt], wf[o][kt][0], wf[o][kt][1]);
                mma16(accN[0], (const uint32_t*)&hf[kt], wf[4][kt][0], wf[4][kt][1]);
                mma16(accN[1], (const uint32_t*)&hf[kt], wf[5][kt][0], wf[5][kt][1]);
            }
        }

        // partial store into buffer (t&1): layout [b][jj][gate]
        float* pb = part + (t & 1) * PBUF;
        {
            float* pw = pb + warp * (16 * PSTRIDE);
            const int r = lane >> 2, c2 = (lane & 3) * 2;
#pragma unroll
            for (int o = 0; o < 6; o++) {
                const int g = o >> 1;
                const int j0 = (o & 1) * 8 + c2;
                pw[r * PSTRIDE + j0 * 4 + g]             = acc[o][0];
                pw[r * PSTRIDE + (j0 + 1) * 4 + g]       = acc[o][1];
                pw[(r + 8) * PSTRIDE + j0 * 4 + g]       = acc[o][2];
                pw[(r + 8) * PSTRIDE + (j0 + 1) * 4 + g] = acc[o][3];
            }
#pragma unroll
            for (int o = 0; o < 2; o++) {
                const int j0 = o * 8 + c2;
                pw[r * PSTRIDE + j0 * 4 + 3]             = accN[o][0];
                pw[r * PSTRIDE + (j0 + 1) * 4 + 3]       = accN[o][1];
                pw[(r + 8) * PSTRIDE + j0 * 4 + 3]       = accN[o][2];
                pw[(r + 8) * PSTRIDE + (j0 + 1) * 4 + 3] = accN[o][3];
            }
        }
        __syncthreads();

        // ======== gates ========
        {
            float sr = c_r, sz = c_z, xn = c_xn, hn = c_hn;
#pragma unroll
            for (int w = 0; w < 8; w++) {
                const float* p = pb + w * (16 * PSTRIDE) + g_b * PSTRIDE + g_jj * 4;
                float2 v01 = *(const float2*)p;
                float2 v23 = *(const float2*)(p + 2);
                sr += v01.x; sz += v01.y; xn += v23.x; hn += v23.y;
            }
            float rg = fast_sigmoid(sr);
            float zg = fast_sigmoid(sz);
            float ng = fast_tanh(xn + rg * hn);
            hstate = (1.f - zg) * ng + zg * hstate;
            __nv_bfloat16 hb = __float2bfloat16(hstate);
            __stcg((__nv_bfloat16*)((char*)houtp + (size_t)t * 32768), hb);
            if (is_l1)
                __stcg(h2r + ((size_t)((g_b << 10) + t)) * 1024 + jbase + g_jj, hb);
        }

        // ======== tail barrier: warps 1-7 run ahead; warp 0 releases ========
        if (warp == 0) {
            asm volatile("bar.sync 1, 256;" ::: "memory");
            if (lane == 0) st_rel(my_cnt, (unsigned)(t + 1));
        } else {
            asm volatile("bar.arrive 1, 256;" ::: "memory");
        }
    }
}

// ===========================================================================
// log_softmax over axis=1 (T)
// ===========================================================================
__global__ void __launch_bounds__(1024) lse_kernel(
    const float* __restrict__ logits, float* __restrict__ lse)
{
    __shared__ float sm_m[1024], sm_s[1024];
    const int b = blockIdx.x;
    const int tid = threadIdx.x;
    const int c = tid & 127, ts = tid >> 7;
    const float* p = logits + ((size_t)((b << 10) + (ts << 7))) * NCLS + c;
    float m = -1e30f, s = 0.f;
    for (int i = 0; i < 128; i++) {
        float x = p[(size_t)i * NCLS];
        if (x > m) { s = s * expf(m - x) + 1.f; m = x; }
        else       { s += expf(x - m); }
    }
    sm_m[tid] = m; sm_s[tid] = s;
    __syncthreads();
    if (tid < 128) {
        float M = sm_m[tid], S = sm_s[tid];
#pragma unroll
        for (int k = 1; k < 8; k++) {
            float m2 = sm_m[tid + k * 128], s2 = sm_s[tid + k * 128];
            if (m2 > M) { S = S * expf(M - m2) + s2; M = m2; }
            else        { S += s2 * expf(m2 - M); }
        }
        lse[b * NCLS + tid] = M + logf(S);
    }
}

__global__ void sub_kernel(float* __restrict__ out, const float* __restrict__ lse)
{
    int idx = blockIdx.x * blockDim.x + threadIdx.x;
    int b = idx >> 17;
    int c = idx & 127;
    out[idx] -= lse[(b << 7) + c];
}

// ===========================================================================
extern "C" void kernel_launch(void* const* d_in, const int* in_sizes, int n_in,
                              void* d_out, int out_size)
{
    (void)in_sizes; (void)n_in; (void)out_size;
    const int*   tok  = (const int*)d_in[0];
    const float* emb  = (const float*)d_in[1];
    const float* Wih0 = (const float*)d_in[2];
    const float* Whh0 = (const float*)d_in[3];
    const float* bih0 = (const float*)d_in[4];
    const float* bhh0 = (const float*)d_in[5];
    const float* Wih1 = (const float*)d_in[6];
    const float* Whh1 = (const float*)d_in[7];
    const float* bih1 = (const float*)d_in[8];
    const float* bhh1 = (const float*)d_in[9];
    const float* Wlin = (const float*)d_in[10];
    const float* blin = (const float*)d_in[11];
    float* out = (float*)d_out;

    float *lseb;
    __nv_bfloat16 *a16f, *h1f, *h2f, *h2r, *b16;
    cudaGetSymbolAddress((void**)&lseb, g_lse);
    cudaGetSymbolAddress((void**)&a16f, g_a16f);
    cudaGetSymbolAddress((void**)&h1f,  g_h1f);
    cudaGetSymbolAddress((void**)&h2f,  g_h2f);
    cudaGetSymbolAddress((void**)&h2r,  g_h2r);
    cudaGetSymbolAddress((void**)&b16,  g_b16);

    cudaFuncSetAttribute(gemm_bf16, cudaFuncAttributeMaxDynamicSharedMemorySize,
                         GEMM_SMEM_BYTES);
    cudaFuncSetAttribute(scan_fused, cudaFuncAttributeMaxDynamicSharedMemorySize,
                         SM_TOTAL);

    const size_t l_tot4 = ((size_t)NCLS * HD) / 4;
    const int CB = 256;

    // Prologue: emb -> fragment-order bf16; head weights -> bf16; counters
    conv_frag<<<(MTOT * HD / 8) / CB, CB>>>(emb, tok, a16f);
    conv_bf16<<<(unsigned)((l_tot4 + CB - 1) / CB), CB>>>(Wlin, b16, l_tot4);
    bar_reset<<<1, 256>>>();

    // Fused two-layer scan
    scan_fused<<<128, 256, SM_TOTAL>>>(a16f, Wih0, bih0, Whh0, bhh0,
                                       Wih1, bih1, Whh1, bhh1, h1f, h2f, h2r);

    // Head
    dim3 gL(MTOT / 128, 1);
    gemm_bf16<<<gL, 256, GEMM_SMEM_BYTES>>>(h2r, b16, blin, out, NCLS);

    // log_softmax over T
    lse_kernel<<<BATCH, 1024>>>(out, lseb);
    sub_kernel<<<(MTOT * NCLS) / 1024, 1024>>>(out, lseb);
}